// round 2
// baseline (speedup 1.0000x reference)
#include <cuda_runtime.h>
#include <math.h>

// Problem constants
#define Bn    64
#define Sn    256
#define En    256
#define Hn    256          // per-direction hidden
#define Gn    1024         // 4*Hn
#define Tn    32
#define NTOK  (Bn*Sn)      // 16384

// ---------------- f32x2 helpers (sm_103a packed fp32) ---------------------------
__device__ __forceinline__ unsigned long long pk2(float lo, float hi) {
    unsigned long long r;
    asm("mov.b64 %0, {%1, %2};" : "=l"(r) : "f"(lo), "f"(hi));
    return r;
}
__device__ __forceinline__ unsigned long long f2fma(unsigned long long a,
                                                    unsigned long long b,
                                                    unsigned long long c) {
    unsigned long long d;
    asm("fma.rn.f32x2 %0, %1, %2, %3;" : "=l"(d) : "l"(a), "l"(b), "l"(c));
    return d;
}
__device__ __forceinline__ unsigned long long f2add(unsigned long long a,
                                                    unsigned long long b) {
    unsigned long long d;
    asm("add.rn.f32x2 %0, %1, %2;" : "=l"(d) : "l"(a), "l"(b));
    return d;
}
__device__ __forceinline__ float2 upk(unsigned long long v) {
    float2 r;
    asm("mov.b64 {%0, %1}, %2;" : "=f"(r.x), "=f"(r.y) : "l"(v));
    return r;
}

// ---------------- scratch (static device globals; no allocation) ----------------
__device__ float g_x[NTOK*En];                 // x[s][b][e], m = s*64+b
__device__ float g_zx[2u*NTOK*Gn];             // Zx[dir][m][1024]
__device__ float g_h[2*2*Bn*Hn];               // h[parity][dir][b][j]
__device__ float g_hseq[2u*Bn*Sn*Hn];          // hseq[dir][b][t][j]
__device__ float g_feats[NTOK*Tn];             // feats[b][s][tag]
__device__ unsigned g_bar_count;               // grid barrier (sense-reversing)
__device__ unsigned g_bar_gen;

// ---------------- 1) embedding gather ------------------------------------------
__global__ void k_embed(const int* __restrict__ sent, const float* __restrict__ emb)
{
    int idx = blockIdx.x * 256 + threadIdx.x;
    int e = idx & 255;
    int m = idx >> 8;            // s*64+b
    int b = m & 63, s = m >> 6;
    int w = sent[b * Sn + s];
    g_x[idx] = emb[(size_t)w * En + e];
}

// ---------------- 2) Zx GEMM (FFMA2): C[m][n] = X[m]·W[n] + bias[n] -------------
__global__ __launch_bounds__(256, 2)
void k_gemm(const float* __restrict__ W, const float* __restrict__ bias, int dir)
{
    __shared__ float As[16][128];
    __shared__ float Bs[16][128];

    const int tid  = threadIdx.x;
    const int bm   = blockIdx.x << 7;
    const int bn   = blockIdx.y << 7;
    const int warp = tid >> 5, lane = tid & 31;
    const int tm   = ((warp & 3) << 5) + ((lane >> 3) << 3);
    const int tn   = ((warp >> 2) << 6) + ((lane & 7) << 3);
    const int lr   = tid >> 2;
    const int lc   = tid & 3;

    unsigned long long acc2[8][4];
#pragma unroll
    for (int i = 0; i < 8; i++)
#pragma unroll
        for (int j = 0; j < 4; j++) acc2[i][j] = 0ull;

    for (int k0 = 0; k0 < En; k0 += 16) {
#pragma unroll
        for (int r = 0; r < 2; r++) {
            int mrow = bm + lr + (r << 6);
            float4 v = *(const float4*)(g_x + (size_t)mrow * En + k0 + (lc << 2));
            As[(lc << 2) + 0][lr + (r << 6)] = v.x;
            As[(lc << 2) + 1][lr + (r << 6)] = v.y;
            As[(lc << 2) + 2][lr + (r << 6)] = v.z;
            As[(lc << 2) + 3][lr + (r << 6)] = v.w;
            int nrow = bn + lr + (r << 6);
            float4 wv = *(const float4*)(W + (size_t)nrow * En + k0 + (lc << 2));
            Bs[(lc << 2) + 0][lr + (r << 6)] = wv.x;
            Bs[(lc << 2) + 1][lr + (r << 6)] = wv.y;
            Bs[(lc << 2) + 2][lr + (r << 6)] = wv.z;
            Bs[(lc << 2) + 3][lr + (r << 6)] = wv.w;
        }
        __syncthreads();
#pragma unroll
        for (int kk = 0; kk < 16; kk++) {
            float a[8];
            *(float4*)(a)     = *(const float4*)&As[kk][tm];
            *(float4*)(a + 4) = *(const float4*)&As[kk][tm + 4];
            ulonglong2 b01 = *(const ulonglong2*)&Bs[kk][tn];
            ulonglong2 b23 = *(const ulonglong2*)&Bs[kk][tn + 4];
#pragma unroll
            for (int i = 0; i < 8; i++) {
                unsigned long long ad = pk2(a[i], a[i]);
                acc2[i][0] = f2fma(ad, b01.x, acc2[i][0]);
                acc2[i][1] = f2fma(ad, b01.y, acc2[i][1]);
                acc2[i][2] = f2fma(ad, b23.x, acc2[i][2]);
                acc2[i][3] = f2fma(ad, b23.y, acc2[i][3]);
            }
        }
        __syncthreads();
    }

    float bv[8];
#pragma unroll
    for (int j = 0; j < 8; j++) bv[j] = bias[bn + tn + j];

    float* C = g_zx + (size_t)dir * NTOK * Gn;
#pragma unroll
    for (int i = 0; i < 8; i++) {
        size_t off = (size_t)(bm + tm + i) * Gn + bn + tn;
        float2 c0 = upk(acc2[i][0]);
        float2 c1 = upk(acc2[i][1]);
        float2 c2 = upk(acc2[i][2]);
        float2 c3 = upk(acc2[i][3]);
        float4 o0 = make_float4(c0.x + bv[0], c0.y + bv[1], c1.x + bv[2], c1.y + bv[3]);
        float4 o1 = make_float4(c2.x + bv[4], c2.y + bv[5], c3.x + bv[6], c3.y + bv[7]);
        *(float4*)(C + off)     = o0;
        *(float4*)(C + off + 4) = o1;
    }
}

// ---------------- 3) persistent bidirectional LSTM (128 blocks) -----------------
// block = (dir, 4 hidden units). 512 threads = (b 0..63, jj 0..3, gh 0..1).
// W staged PRE-PAIRED: pair gh covers gates (2gh, 2gh+1) packed as f32x2.
// Accumulate packed gate pairs; exchange (g,o) to (i,f) owner via shfl.xor(1).
#define WS_STRIDE 516          // floats per (pair,jj) row (512 data + pad; %32 == 4)
#define HS_STRIDE 260          // padded staged-h row
#define SMEM_LSTM ((8*WS_STRIDE + Bn*HS_STRIDE) * sizeof(float))

__global__ __launch_bounds__(512)
void k_lstm(const float* __restrict__ Whh_f, const float* __restrict__ Whh_b)
{
    extern __shared__ float smx[];
    float* Ws = smx;                     // [2 pair][4 jj][WS_STRIDE]
    float* hs = smx + 8 * WS_STRIDE;     // [64 b][HS_STRIDE]

    const int tid = threadIdx.x;
    const int dir = blockIdx.x >> 6;
    const int j0  = (blockIdx.x & 63) << 2;
    const int b   = tid >> 3;
    const int jj  = (tid >> 1) & 3;
    const int gh  = tid & 1;

    const float* Whh = dir ? Whh_b : Whh_f;
    // Stage W pre-paired: Ws[(p*4+j2)*WS + 2k + e] = Whh[(2p+e) gate, j0+j2, k]
    for (int idx = tid; idx < 4096; idx += 512) {
        int e  = idx & 1;
        int k  = (idx >> 1) & 255;
        int j2 = (idx >> 9) & 3;
        int p  = idx >> 11;
        Ws[(p * 4 + j2) * WS_STRIDE + 2 * k + e] =
            Whh[((2 * p + e) * Hn + j0 + j2) * Hn + k];
    }

    // zero h(parity 0) slice (gh==0 threads own the 256 outputs)
    if (gh == 0)
        g_h[(0 * 2 + dir) * (Bn * Hn) + b * Hn + j0 + jj] = 0.f;

    float c = 0.f;
    volatile unsigned* vgen = &g_bar_gen;
    unsigned gen = *vgen;

#define GRID_BAR() do {                                                   \
        __syncthreads();                                                  \
        if (tid == 0) {                                                   \
            __threadfence();                                              \
            unsigned tgt = ++gen;                                         \
            if (atomicAdd(&g_bar_count, 1u) == 127u) {                    \
                g_bar_count = 0u;                                         \
                __threadfence();                                          \
                atomicAdd(&g_bar_gen, 1u);                                \
            } else {                                                      \
                while (*vgen != tgt) { }                                  \
                __threadfence();                                          \
            }                                                             \
        }                                                                 \
        __syncthreads();                                                  \
    } while (0)

    GRID_BAR();   // h0 visible everywhere

    const size_t zdir = (size_t)dir * NTOK * Gn;
    const float* wrow = Ws + (gh * 4 + jj) * WS_STRIDE;
    const float* hrow = hs + b * HS_STRIDE;

    // prefetched z for the first step (gates 2gh, 2gh+1 at column j0+jj)
    {
        int t0 = dir ? (Sn - 1) : 0;
        const float* zr = g_zx + zdir + ((size_t)(t0 * Bn + b) << 10)
                        + (gh << 9) + j0 + jj;
        // loaded below into zlo/zhi
    }
    int tfirst = dir ? (Sn - 1) : 0;
    const float* zr0 = g_zx + zdir + ((size_t)(tfirst * Bn + b) << 10)
                     + (gh << 9) + j0 + jj;
    float zlo = zr0[0], zhi = zr0[256];

    for (int st = 0; st < Sn; ++st) {
        const int t   = dir ? (Sn - 1 - st) : st;
        const int par = st & 1;

        // stage h[par][dir] (64KB) into smem
        const float4* hp = (const float4*)(g_h + (par * 2 + dir) * (Bn * Hn));
#pragma unroll
        for (int i = 0; i < 8; i++) {
            int li = tid + (i << 9);
            float4 v = hp[li];
            int bb = li >> 6, kk = li & 63;
            *(float4*)(hs + bb * HS_STRIDE + (kk << 2)) = v;
        }
        __syncthreads();

        unsigned long long acc_a = pk2(zlo, zhi);
        unsigned long long acc_b = 0ull;

#pragma unroll 8
        for (int k = 0; k < Hn; k += 4) {
            float4 hv = *(const float4*)(hrow + k);
            ulonglong2 w01 = *(const ulonglong2*)(wrow + 2 * k);
            ulonglong2 w23 = *(const ulonglong2*)(wrow + 2 * k + 4);
            acc_a = f2fma(pk2(hv.x, hv.x), w01.x, acc_a);
            acc_b = f2fma(pk2(hv.y, hv.y), w01.y, acc_b);
            acc_a = f2fma(pk2(hv.z, hv.z), w23.x, acc_a);
            acc_b = f2fma(pk2(hv.w, hv.w), w23.y, acc_b);
        }
        unsigned long long s = f2add(acc_a, acc_b);

        // prefetch next step's z NOW (latency hides under shfl/MUFU/barrier)
        if (st + 1 < Sn) {
            int tn2 = dir ? (Sn - 2 - st) : (st + 1);
            const float* zr = g_zx + zdir + ((size_t)(tn2 * Bn + b) << 10)
                            + (gh << 9) + j0 + jj;
            zlo = zr[0]; zhi = zr[256];
        }

        // exchange gate pairs: gh0 holds (i,f), gh1 holds (g,o)
        unsigned long long other = __shfl_xor_sync(0xffffffffu, s, 1);

        if (gh == 0) {
            float2 sif = upk(s);
            float2 sgo = upk(other);
            float ig = 1.f / (1.f + expf(-sif.x));
            float fg = 1.f / (1.f + expf(-sif.y));
            float gg = tanhf(sgo.x);
            float og = 1.f / (1.f + expf(-sgo.y));
            c = fg * c + ig * gg;
            float hn = og * tanhf(c);

            int j = j0 + jj;
            g_h[((par ^ 1) * 2 + dir) * (Bn * Hn) + b * Hn + j] = hn;
            g_hseq[(((size_t)dir * Bn + b) * Sn + t) * Hn + j] = hn;
        }

        GRID_BAR();
    }
#undef GRID_BAR
}

// ---------------- 4) feats = concat(h_f,h_b) @ Wout^T + bout -------------------
__global__ __launch_bounds__(256)
void k_feats(const float* __restrict__ Wout, const float* __restrict__ bout)
{
    __shared__ float Wt[128][33];

    const int tid = threadIdx.x;
    const int tag = tid & 31;
    const int ti  = tid >> 5;
    const int m   = blockIdx.x * 8 + ti;
    const int bb  = m & 63, ss = m >> 6;

    float acc = bout[tag];

    for (int cch = 0; cch < 4; cch++) {
        __syncthreads();
        for (int i = tid; i < 1024; i += 256) {
            int r = i >> 5;
            int k4 = i & 31;
            float4 w = *(const float4*)(Wout + (size_t)r * 512 + cch * 128 + (k4 << 2));
            Wt[(k4 << 2) + 0][r] = w.x;
            Wt[(k4 << 2) + 1][r] = w.y;
            Wt[(k4 << 2) + 2][r] = w.z;
            Wt[(k4 << 2) + 3][r] = w.w;
        }
        __syncthreads();

        const float* hrow;
        if (cch < 2)
            hrow = g_hseq + (((size_t)0 * Bn + bb) * Sn + ss) * Hn + cch * 128;
        else
            hrow = g_hseq + (((size_t)1 * Bn + bb) * Sn + ss) * Hn + (cch - 2) * 128;

#pragma unroll 8
        for (int k = 0; k < 128; k += 4) {
            float4 hv = *(const float4*)(hrow + k);
            acc += hv.x * Wt[k + 0][tag];
            acc += hv.y * Wt[k + 1][tag];
            acc += hv.z * Wt[k + 2][tag];
            acc += hv.w * Wt[k + 3][tag];
        }
    }
    g_feats[((size_t)(bb * Sn) + ss) * Tn + tag] = acc;
}

// ---------------- 5) Viterbi: one warp per batch ------------------------------
__global__ void k_viterbi(const float* __restrict__ trans, float* __restrict__ out)
{
    __shared__ float tr[32][32];
    __shared__ unsigned char bp[Sn][32];

    const int b   = blockIdx.x;
    const int tag = threadIdx.x;

    for (int p = 0; p < 32; p++) tr[p][tag] = trans[p * 32 + tag];
    __syncwarp();

    float v = (tag == 0) ? 0.f : -10000.f;
    const float* fb = g_feats + (size_t)b * Sn * Tn;

    for (int t = 0; t < Sn; t++) {
        float best = -3.4e38f; int arg = 0;
#pragma unroll
        for (int p = 0; p < 32; p++) {
            float vp = __shfl_sync(0xffffffffu, v, p);
            float sc = vp + tr[p][tag];
            if (sc > best) { best = sc; arg = p; }
        }
        bp[t][tag] = (unsigned char)arg;
        v = best + fb[t * 32 + tag];
    }

    float term = v + tr[0][tag];
    float best = -3.4e38f; int lt = 0;
#pragma unroll
    for (int p = 0; p < 32; p++) {
        float tp = __shfl_sync(0xffffffffu, term, p);
        if (tp > best) { best = tp; lt = p; }
    }
    __syncwarp();

    if (tag == 0) {
        int cur = lt;
        for (int t = Sn - 1; t >= 1; --t) {
            out[b * Sn + t] = (float)cur;
            cur = bp[t][cur];
        }
        out[b * Sn + 0] = (float)cur;
        out[NTOK + b]   = best;
    }
}

// ---------------- launcher -----------------------------------------------------
extern "C" void kernel_launch(void* const* d_in, const int* in_sizes, int n_in,
                              void* d_out, int out_size)
{
    const int*   sent  = (const int*)  d_in[0];
    const float* embed = (const float*)d_in[1];
    const float* Wih_f = (const float*)d_in[2];
    const float* Whh_f = (const float*)d_in[3];
    const float* b_f   = (const float*)d_in[4];
    const float* Wih_b = (const float*)d_in[5];
    const float* Whh_b = (const float*)d_in[6];
    const float* b_b   = (const float*)d_in[7];
    const float* Wout  = (const float*)d_in[8];
    const float* bout  = (const float*)d_in[9];
    const float* trans = (const float*)d_in[10];
    float* out = (float*)d_out;
    (void)in_sizes; (void)n_in; (void)out_size;

    // 1) embedding
    k_embed<<<NTOK, 256>>>(sent, embed);

    // 2) input-side GEMMs (both directions), hoisted out of the recurrence
    dim3 gg(NTOK / 128, Gn / 128);
    k_gemm<<<gg, 256>>>(Wih_f, b_f, 0);
    k_gemm<<<gg, 256>>>(Wih_b, b_b, 1);

    // 3) persistent recurrent kernel (128 co-resident blocks + grid barrier)
    cudaFuncSetAttribute(k_lstm, cudaFuncAttributeMaxDynamicSharedMemorySize,
                         (int)SMEM_LSTM);
    k_lstm<<<128, 512, SMEM_LSTM>>>(Whh_f, Whh_b);

    // 4) emissions
    k_feats<<<NTOK / 8, 256>>>(Wout, bout);

    // 5) viterbi decode + writeback (paths as float, then scores)
    k_viterbi<<<Bn, 32>>>(trans, out);
}

// round 4
// speedup vs baseline: 1.7755x; 1.7755x over previous
#include <cuda_runtime.h>
#include <math.h>

// Problem constants
#define Bn    64
#define Sn    256
#define En    256
#define Hn    256          // per-direction hidden
#define Gn    1024         // 4*Hn
#define Tn    32
#define NTOK  (Bn*Sn)      // 16384

// ---------------- scratch (static device globals; no allocation) ----------------
__device__ float g_x[NTOK*En];                 // x[s][b][e], m = s*64+b
__device__ float g_zx[2u*NTOK*Gn];             // Zx[dir][m][1024]
__device__ float g_h[2*2*Bn*Hn];               // h[parity][dir][b][j]
__device__ float g_hseq[2u*Bn*Sn*Hn];          // hseq[dir][b][t][j]
__device__ float g_feats[NTOK*Tn];             // feats[b][s][tag]
__device__ unsigned g_bc[2];                   // per-direction grid barrier
__device__ unsigned g_bg[2];

// ---------------- 1) embedding gather ------------------------------------------
__global__ void k_embed(const int* __restrict__ sent, const float* __restrict__ emb)
{
    int idx = blockIdx.x * 256 + threadIdx.x;
    int e = idx & 255;
    int m = idx >> 8;            // s*64+b
    int b = m & 63, s = m >> 6;
    int w = sent[b * Sn + s];
    g_x[idx] = emb[(size_t)w * En + e];
}

// ---------------- 2) Zx GEMM: C[m][n] = X[m]·W[n] + bias[n] (scalar FFMA) -------
__global__ __launch_bounds__(256, 2)
void k_gemm(const float* __restrict__ W, const float* __restrict__ bias, int dir)
{
    __shared__ float As[16][128];
    __shared__ float Bs[16][128];

    const int tid  = threadIdx.x;
    const int bm   = blockIdx.x << 7;
    const int bn   = blockIdx.y << 7;
    const int warp = tid >> 5, lane = tid & 31;
    const int tm   = ((warp & 3) << 5) + ((lane >> 3) << 3);
    const int tn   = ((warp >> 2) << 6) + ((lane & 7) << 3);
    const int lr   = tid >> 2;
    const int lc   = tid & 3;

    float acc[8][8];
#pragma unroll
    for (int i = 0; i < 8; i++)
#pragma unroll
        for (int j = 0; j < 8; j++) acc[i][j] = 0.f;

    for (int k0 = 0; k0 < En; k0 += 16) {
#pragma unroll
        for (int r = 0; r < 2; r++) {
            int mrow = bm + lr + (r << 6);
            float4 v = *(const float4*)(g_x + (size_t)mrow * En + k0 + (lc << 2));
            As[(lc << 2) + 0][lr + (r << 6)] = v.x;
            As[(lc << 2) + 1][lr + (r << 6)] = v.y;
            As[(lc << 2) + 2][lr + (r << 6)] = v.z;
            As[(lc << 2) + 3][lr + (r << 6)] = v.w;
            int nrow = bn + lr + (r << 6);
            float4 wv = *(const float4*)(W + (size_t)nrow * En + k0 + (lc << 2));
            Bs[(lc << 2) + 0][lr + (r << 6)] = wv.x;
            Bs[(lc << 2) + 1][lr + (r << 6)] = wv.y;
            Bs[(lc << 2) + 2][lr + (r << 6)] = wv.z;
            Bs[(lc << 2) + 3][lr + (r << 6)] = wv.w;
        }
        __syncthreads();
#pragma unroll
        for (int kk = 0; kk < 16; kk++) {
            float a[8], bb[8];
            *(float4*)(a)      = *(const float4*)&As[kk][tm];
            *(float4*)(a + 4)  = *(const float4*)&As[kk][tm + 4];
            *(float4*)(bb)     = *(const float4*)&Bs[kk][tn];
            *(float4*)(bb + 4) = *(const float4*)&Bs[kk][tn + 4];
#pragma unroll
            for (int i = 0; i < 8; i++)
#pragma unroll
                for (int j = 0; j < 8; j++)
                    acc[i][j] += a[i] * bb[j];
        }
        __syncthreads();
    }

    float bv[8];
#pragma unroll
    for (int j = 0; j < 8; j++) bv[j] = bias[bn + tn + j];

    float* C = g_zx + (size_t)dir * NTOK * Gn;
#pragma unroll
    for (int i = 0; i < 8; i++) {
        size_t off = (size_t)(bm + tm + i) * Gn + bn + tn;
        float4 o0 = make_float4(acc[i][0] + bv[0], acc[i][1] + bv[1],
                                acc[i][2] + bv[2], acc[i][3] + bv[3]);
        float4 o1 = make_float4(acc[i][4] + bv[4], acc[i][5] + bv[5],
                                acc[i][6] + bv[6], acc[i][7] + bv[7]);
        *(float4*)(C + off)     = o0;
        *(float4*)(C + off + 4) = o1;
    }
}

// ---------------- 3) persistent bidirectional LSTM (128 blocks, 512 thr) --------
// block = (dir, 4 hidden units). thread = (b 0..63, jj 0..3, kh 0..1).
// Each thread accumulates all 4 gates over its k-half (128 of 256), then
// combines with its partner via shfl.xor(1). Per-direction grid barrier.
// Smem rows padded so (jj, kh) lanes hit 8 distinct 4-bank groups (conflict-free):
//   row stride 264 floats (mod 32 == 8), k-half offset 132 floats (mod 32 == 4).
#define RS 264
#define KHO 132
#define SMEM_LSTM ((16*RS + Bn*RS) * sizeof(float))

__global__ __launch_bounds__(512)
void k_lstm(const float* __restrict__ Whh_f, const float* __restrict__ Whh_b)
{
    extern __shared__ float smx[];
    float* Ws = smx;               // [4 gates][4 jj][RS]  (each row: 2 k-halves)
    float* hs = smx + 16 * RS;     // [64 b][RS]

    const int tid = threadIdx.x;
    const int dir = blockIdx.x >> 6;
    const int j0  = (blockIdx.x & 63) << 2;
    const int b   = tid >> 3;
    const int jj  = (tid >> 1) & 3;
    const int kh  = tid & 1;

    const float* Whh = dir ? Whh_b : Whh_f;
    for (int idx = tid; idx < 4096; idx += 512) {
        int g = idx >> 10, j2 = (idx >> 8) & 3, k = idx & 255;
        Ws[(g * 4 + j2) * RS + (k >> 7) * KHO + (k & 127)] =
            Whh[(g * Hn + j0 + j2) * Hn + k];
    }

    // zero h(parity 0) slice
    if (kh == 0)
        g_h[(0 * 2 + dir) * (Bn * Hn) + b * Hn + j0 + jj] = 0.f;

    float c = 0.f;
    volatile unsigned* vgen = &g_bg[dir];
    unsigned gen = *vgen;          // safe: release needs this block's arrival

#define GRID_BAR() do {                                                   \
        __syncthreads();                                                  \
        if (tid == 0) {                                                   \
            __threadfence();                                              \
            unsigned tgt = ++gen;                                         \
            if (atomicAdd(&g_bc[dir], 1u) == 63u) {                       \
                g_bc[dir] = 0u;                                           \
                __threadfence();                                          \
                atomicAdd(&g_bg[dir], 1u);                                \
            } else {                                                      \
                while (*vgen != tgt) { }                                  \
                __threadfence();                                          \
            }                                                             \
        }                                                                 \
        __syncthreads();                                                  \
    } while (0)

    GRID_BAR();   // h0 visible everywhere

    const size_t zdir = (size_t)dir * NTOK * Gn;
    const float* hrow = hs + b * RS + kh * KHO;
    const float* w0 = Ws + (0 * 4 + jj) * RS + kh * KHO;
    const float* w1 = Ws + (1 * 4 + jj) * RS + kh * KHO;
    const float* w2 = Ws + (2 * 4 + jj) * RS + kh * KHO;
    const float* w3 = Ws + (3 * 4 + jj) * RS + kh * KHO;

    // prefetch z for the first step (only kh==0 folds z in)
    float z0 = 0.f, z1 = 0.f, z2 = 0.f, z3 = 0.f;
    {
        int t0 = dir ? (Sn - 1) : 0;
        const float* zr = g_zx + zdir + ((size_t)(t0 * Bn + b) << 10) + j0 + jj;
        if (kh == 0) { z0 = zr[0]; z1 = zr[256]; z2 = zr[512]; z3 = zr[768]; }
    }

    for (int st = 0; st < Sn; ++st) {
        const int t   = dir ? (Sn - 1 - st) : st;
        const int par = st & 1;

        // stage h[par][dir] (64KB) into smem, split-k padded layout
        const float4* hp = (const float4*)(g_h + (par * 2 + dir) * (Bn * Hn));
#pragma unroll
        for (int i = 0; i < 8; i++) {
            int li = tid + (i << 9);
            float4 v = hp[li];
            int bb = li >> 6, kk = li & 63;            // kk = float4 index in row
            int khh = kk >> 5, kr = (kk & 31) << 2;
            *(float4*)(hs + bb * RS + khh * KHO + kr) = v;
        }
        __syncthreads();

        float a0 = z0, a1 = z1, a2 = z2, a3 = z3;
#pragma unroll 8
        for (int k = 0; k < 128; k += 4) {
            float4 hv = *(const float4*)(hrow + k);
            float4 wv;
            wv = *(const float4*)(w0 + k);
            a0 += hv.x * wv.x + hv.y * wv.y + hv.z * wv.z + hv.w * wv.w;
            wv = *(const float4*)(w1 + k);
            a1 += hv.x * wv.x + hv.y * wv.y + hv.z * wv.z + hv.w * wv.w;
            wv = *(const float4*)(w2 + k);
            a2 += hv.x * wv.x + hv.y * wv.y + hv.z * wv.z + hv.w * wv.w;
            wv = *(const float4*)(w3 + k);
            a3 += hv.x * wv.x + hv.y * wv.y + hv.z * wv.z + hv.w * wv.w;
        }

        // prefetch next step's z NOW (DRAM latency hides under combine+barrier)
        if (st + 1 < Sn) {
            int tn2 = dir ? (Sn - 2 - st) : (st + 1);
            const float* zr = g_zx + zdir + ((size_t)(tn2 * Bn + b) << 10) + j0 + jj;
            if (kh == 0) { z0 = zr[0]; z1 = zr[256]; z2 = zr[512]; z3 = zr[768]; }
        }

        // combine k-halves (symmetric: both lanes get identical sums)
        a0 += __shfl_xor_sync(0xffffffffu, a0, 1);
        a1 += __shfl_xor_sync(0xffffffffu, a1, 1);
        a2 += __shfl_xor_sync(0xffffffffu, a2, 1);
        a3 += __shfl_xor_sync(0xffffffffu, a3, 1);

        float ig = 1.f / (1.f + expf(-a0));
        float fg = 1.f / (1.f + expf(-a1));
        float gg = tanhf(a2);
        float og = 1.f / (1.f + expf(-a3));
        c = fg * c + ig * gg;
        float hn = og * tanhf(c);

        int j = j0 + jj;
        if (kh == 0)
            g_h[((par ^ 1) * 2 + dir) * (Bn * Hn) + b * Hn + j] = hn;
        else
            g_hseq[(((size_t)dir * Bn + b) * Sn + t) * Hn + j] = hn;

        GRID_BAR();
    }
#undef GRID_BAR
}

// ---------------- 4) feats = concat(h_f,h_b) @ Wout^T + bout -------------------
__global__ __launch_bounds__(256)
void k_feats(const float* __restrict__ Wout, const float* __restrict__ bout)
{
    __shared__ float Wt[128][33];

    const int tid = threadIdx.x;
    const int tag = tid & 31;
    const int ti  = tid >> 5;
    const int m   = blockIdx.x * 8 + ti;
    const int bb  = m & 63, ss = m >> 6;

    float acc = bout[tag];

    for (int cch = 0; cch < 4; cch++) {
        __syncthreads();
        for (int i = tid; i < 1024; i += 256) {
            int r = i >> 5;
            int k4 = i & 31;
            float4 w = *(const float4*)(Wout + (size_t)r * 512 + cch * 128 + (k4 << 2));
            Wt[(k4 << 2) + 0][r] = w.x;
            Wt[(k4 << 2) + 1][r] = w.y;
            Wt[(k4 << 2) + 2][r] = w.z;
            Wt[(k4 << 2) + 3][r] = w.w;
        }
        __syncthreads();

        const float* hrow;
        if (cch < 2)
            hrow = g_hseq + (((size_t)0 * Bn + bb) * Sn + ss) * Hn + cch * 128;
        else
            hrow = g_hseq + (((size_t)1 * Bn + bb) * Sn + ss) * Hn + (cch - 2) * 128;

#pragma unroll 8
        for (int k = 0; k < 128; k += 4) {
            float4 hv = *(const float4*)(hrow + k);
            acc += hv.x * Wt[k + 0][tag];
            acc += hv.y * Wt[k + 1][tag];
            acc += hv.z * Wt[k + 2][tag];
            acc += hv.w * Wt[k + 3][tag];
        }
    }
    g_feats[((size_t)(bb * Sn) + ss) * Tn + tag] = acc;
}

// ---------------- 5) Viterbi: one warp per batch ------------------------------
__global__ void k_viterbi(const float* __restrict__ trans, float* __restrict__ out)
{
    __shared__ float tr[32][32];
    __shared__ unsigned char bp[Sn][32];

    const int b   = blockIdx.x;
    const int tag = threadIdx.x;

    for (int p = 0; p < 32; p++) tr[p][tag] = trans[p * 32 + tag];
    __syncwarp();

    float v = (tag == 0) ? 0.f : -10000.f;
    const float* fb = g_feats + (size_t)b * Sn * Tn;

    for (int t = 0; t < Sn; t++) {
        float best = -3.4e38f; int arg = 0;
#pragma unroll
        for (int p = 0; p < 32; p++) {
            float vp = __shfl_sync(0xffffffffu, v, p);
            float sc = vp + tr[p][tag];
            if (sc > best) { best = sc; arg = p; }
        }
        bp[t][tag] = (unsigned char)arg;
        v = best + fb[t * 32 + tag];
    }

    float term = v + tr[0][tag];
    float best = -3.4e38f; int lt = 0;
#pragma unroll
    for (int p = 0; p < 32; p++) {
        float tp = __shfl_sync(0xffffffffu, term, p);
        if (tp > best) { best = tp; lt = p; }
    }
    __syncwarp();

    if (tag == 0) {
        int cur = lt;
        for (int t = Sn - 1; t >= 1; --t) {
            out[b * Sn + t] = (float)cur;
            cur = bp[t][cur];
        }
        out[b * Sn + 0] = (float)cur;
        out[NTOK + b]   = best;
    }
}

// ---------------- launcher -----------------------------------------------------
extern "C" void kernel_launch(void* const* d_in, const int* in_sizes, int n_in,
                              void* d_out, int out_size)
{
    const int*   sent  = (const int*)  d_in[0];
    const float* embed = (const float*)d_in[1];
    const float* Wih_f = (const float*)d_in[2];
    const float* Whh_f = (const float*)d_in[3];
    const float* b_f   = (const float*)d_in[4];
    const float* Wih_b = (const float*)d_in[5];
    const float* Whh_b = (const float*)d_in[6];
    const float* b_b   = (const float*)d_in[7];
    const float* Wout  = (const float*)d_in[8];
    const float* bout  = (const float*)d_in[9];
    const float* trans = (const float*)d_in[10];
    float* out = (float*)d_out;
    (void)in_sizes; (void)n_in; (void)out_size;

    // 1) embedding
    k_embed<<<NTOK, 256>>>(sent, embed);

    // 2) input-side GEMMs (both directions), hoisted out of the recurrence
    dim3 gg(NTOK / 128, Gn / 128);
    k_gemm<<<gg, 256>>>(Wih_f, b_f, 0);
    k_gemm<<<gg, 256>>>(Wih_b, b_b, 1);

    // 3) persistent recurrent kernel (128 co-resident blocks, per-dir barriers)
    cudaFuncSetAttribute(k_lstm, cudaFuncAttributeMaxDynamicSharedMemorySize,
                         (int)SMEM_LSTM);
    k_lstm<<<128, 512, SMEM_LSTM>>>(Whh_f, Whh_b);

    // 4) emissions
    k_feats<<<NTOK / 8, 256>>>(Wout, bout);

    // 5) viterbi decode + writeback (paths as float, then scores)
    k_viterbi<<<Bn, 32>>>(trans, out);
}

// round 6
// speedup vs baseline: 1.9773x; 1.1136x over previous
#include <cuda_runtime.h>
#include <cuda_bf16.h>
#include <math.h>
#include <cstdint>

// Problem constants
#define Bn    64
#define Sn    256
#define En    256
#define Hn    256          // per-direction hidden
#define Gn    1024         // 4*Hn
#define Tn    32
#define NTOK  (Bn*Sn)      // 16384
#define KTOT  768          // 3*En  (hi/lo split GEMM K)
#define KC    32           // K per chunk (bf16)
#define NCH   (KTOT/KC)    // 24 chunks

// ---------------- scratch (static device globals; no allocation) ----------------
__device__ __align__(256) __nv_bfloat16 gA[(size_t)NTOK*KTOT];   // [m][768]
__device__ __align__(256) __nv_bfloat16 gB[(size_t)2*Gn*KTOT];   // [dir][n][768]
__device__ float g_zx[2u*NTOK*Gn];             // Zx[dir][m][1024]
__device__ float g_h[2*2*Bn*Hn];               // h[parity][dir][b][j]
__device__ float g_hseq[2u*Bn*Sn*Hn];          // hseq[dir][b][t][j]
__device__ float g_feats[NTOK*Tn];             // feats[b][s][tag]
__device__ unsigned g_bc[2];                   // per-direction grid barrier
__device__ unsigned g_bg[2];

// ---------------- helpers -------------------------------------------------------
__device__ __forceinline__ uint32_t smem_u32(const void* p) {
    uint32_t a;
    asm("{ .reg .u64 t; cvta.to.shared.u64 t, %1; cvt.u32.u64 %0, t; }"
        : "=r"(a) : "l"(p));
    return a;
}
// 64B-row swizzle: XOR 16B-column bits with row bits 1-2
__device__ __forceinline__ uint32_t swz(uint32_t o) { return o ^ ((o >> 3) & 0x30); }

#define LDSM4(r, a) \
    asm volatile("ldmatrix.sync.aligned.m8n8.x4.shared.b16 {%0,%1,%2,%3}, [%4];" \
        : "=r"((r)[0]), "=r"((r)[1]), "=r"((r)[2]), "=r"((r)[3]) : "r"(a))

#define MMA16816(c, a, bv0, bv1) \
    asm volatile("mma.sync.aligned.m16n8k16.row.col.f32.bf16.bf16.f32 " \
        "{%0,%1,%2,%3}, {%4,%5,%6,%7}, {%8,%9}, {%0,%1,%2,%3};" \
        : "+f"((c)[0]), "+f"((c)[1]), "+f"((c)[2]), "+f"((c)[3]) \
        : "r"((a)[0]), "r"((a)[1]), "r"((a)[2]), "r"((a)[3]), "r"(bv0), "r"(bv1))

// ---------------- 1) embedding gather + hi/lo bf16 split ------------------------
// gA[m] = [xh | xh | xl]
__global__ void k_embed(const int* __restrict__ sent, const float* __restrict__ emb)
{
    int m = blockIdx.x;          // s*64+b
    int e = threadIdx.x;
    int b = m & 63, s = m >> 6;
    int w = sent[b * Sn + s];
    float x = emb[(size_t)w * En + e];
    __nv_bfloat16 xh = __float2bfloat16(x);
    __nv_bfloat16 xl = __float2bfloat16(x - __bfloat162float(xh));
    size_t base = (size_t)m * KTOT;
    gA[base + e]       = xh;
    gA[base + 256 + e] = xh;
    gA[base + 512 + e] = xl;
}

// ---------------- 1b) Wih hi/lo split: gB[dir][n] = [Wh | Wl | Wh] --------------
__global__ void k_wconv(const float* __restrict__ Wf, const float* __restrict__ Wb)
{
    int n   = blockIdx.x & (Gn - 1);
    int dir = blockIdx.x >> 10;
    int k   = threadIdx.x;
    const float* W = dir ? Wb : Wf;
    float w = W[(size_t)n * En + k];
    __nv_bfloat16 wh = __float2bfloat16(w);
    __nv_bfloat16 wl = __float2bfloat16(w - __bfloat162float(wh));
    size_t base = ((size_t)dir * Gn + n) * KTOT;
    gB[base + k]       = wh;
    gB[base + 256 + k] = wl;
    gB[base + 512 + k] = wh;
}

// ---------------- 2) HMMA GEMM: Zx = A·B^T + bias -------------------------------
// CTA 128x128, 8 warps (warp tile 32x64), K chunks of 32, double-buffered smem.
__global__ __launch_bounds__(256)
void k_gemm_mma(const float* __restrict__ bias_f, const float* __restrict__ bias_b)
{
    __shared__ __align__(128) __nv_bfloat16 smA[2][128 * KC];
    __shared__ __align__(128) __nv_bfloat16 smB[2][128 * KC];

    const int tid  = threadIdx.x;
    const int wid  = tid >> 5, lane = tid & 31;
    const int bm   = blockIdx.x << 7;
    const int bn   = blockIdx.y << 7;
    const int dir  = blockIdx.z;
    const int wm   = (wid & 3) << 5;     // warp M offset (0..96)
    const int wn   = (wid >> 2) << 6;    // warp N offset (0/64)

    const char* Agc = (const char*)(gA + (size_t)bm * KTOT);
    const char* Bgc = (const char*)(gB + ((size_t)dir * Gn + bn) * KTOT);

    // loader: thread covers rows (tid>>2) and (tid>>2)+64, 16B chunk tid&3
    const int lrow = tid >> 2, lc16 = tid & 3;
    const uint32_t st0 = swz((uint32_t)lrow * 64 + (lc16 << 4));
    const uint32_t st1 = swz((uint32_t)(lrow + 64) * 64 + (lc16 << 4));
    const size_t ga0 = (size_t)lrow * (KTOT * 2) + (lc16 << 4);
    const size_t ga1 = (size_t)(lrow + 64) * (KTOT * 2) + (lc16 << 4);

    const uint32_t sA0 = smem_u32(smA[0]), sA1 = smem_u32(smA[1]);
    const uint32_t sB0 = smem_u32(smB[0]), sB1 = smem_u32(smB[1]);

    // ldmatrix smem offsets (swizzled), fixed per thread
    uint32_t offA[2][2], offB[4][2];
#pragma unroll
    for (int mt = 0; mt < 2; mt++)
#pragma unroll
        for (int s = 0; s < 2; s++)
            offA[mt][s] = swz((uint32_t)(wm + mt * 16 + (lane & 15)) * 64
                              + s * 32 + ((lane >> 4) << 4));
#pragma unroll
    for (int p = 0; p < 4; p++)
#pragma unroll
        for (int s = 0; s < 2; s++)
            offB[p][s] = swz((uint32_t)(wn + (p << 4) + (lane & 7)
                              + ((lane >> 4) << 3)) * 64
                              + s * 32 + (((lane >> 3) & 1) << 4));

    float acc[2][8][4];
#pragma unroll
    for (int i = 0; i < 2; i++)
#pragma unroll
        for (int j = 0; j < 8; j++)
#pragma unroll
            for (int q = 0; q < 4; q++) acc[i][j][q] = 0.f;

    // prologue: load chunk 0 into buffer 0
    {
        uint4 ra0 = *(const uint4*)(Agc + ga0);
        uint4 ra1 = *(const uint4*)(Agc + ga1);
        uint4 rb0 = *(const uint4*)(Bgc + ga0);
        uint4 rb1 = *(const uint4*)(Bgc + ga1);
        *(uint4*)((char*)smA[0] + st0) = ra0;
        *(uint4*)((char*)smA[0] + st1) = ra1;
        *(uint4*)((char*)smB[0] + st0) = rb0;
        *(uint4*)((char*)smB[0] + st1) = rb1;
    }
    __syncthreads();

    for (int ch = 0; ch < NCH; ch++) {
        const int cur = ch & 1;
        const bool more = (ch + 1) < NCH;
        uint4 ra0, ra1, rb0, rb1;
        if (more) {
            size_t ko = (size_t)(ch + 1) * (KC * 2);
            ra0 = *(const uint4*)(Agc + ga0 + ko);
            ra1 = *(const uint4*)(Agc + ga1 + ko);
            rb0 = *(const uint4*)(Bgc + ga0 + ko);
            rb1 = *(const uint4*)(Bgc + ga1 + ko);
        }

        const uint32_t sA = cur ? sA1 : sA0;
        const uint32_t sB = cur ? sB1 : sB0;
#pragma unroll
        for (int s = 0; s < 2; s++) {
            uint32_t a0[4], a1[4];
            LDSM4(a0, sA + offA[0][s]);
            LDSM4(a1, sA + offA[1][s]);
#pragma unroll
            for (int p = 0; p < 4; p++) {
                uint32_t bq[4];
                LDSM4(bq, sB + offB[p][s]);
                MMA16816(acc[0][2 * p],     a0, bq[0], bq[1]);
                MMA16816(acc[0][2 * p + 1], a0, bq[2], bq[3]);
                MMA16816(acc[1][2 * p],     a1, bq[0], bq[1]);
                MMA16816(acc[1][2 * p + 1], a1, bq[2], bq[3]);
            }
        }
        __syncthreads();
        if (more) {
            char* dA = (char*)smA[cur ^ 1];
            char* dB = (char*)smB[cur ^ 1];
            *(uint4*)(dA + st0) = ra0;
            *(uint4*)(dA + st1) = ra1;
            *(uint4*)(dB + st0) = rb0;
            *(uint4*)(dB + st1) = rb1;
        }
        __syncthreads();
    }

    // epilogue: c0:(g,2t) c1:(g,2t+1) c2:(g+8,2t) c3:(g+8,2t+1)
    const float* bias = dir ? bias_b : bias_f;
    float* C = g_zx + (size_t)dir * NTOK * Gn;
    const int g  = lane >> 2, tg = lane & 3;
#pragma unroll
    for (int mt = 0; mt < 2; mt++) {
        int r0 = bm + wm + mt * 16 + g;
#pragma unroll
        for (int nt = 0; nt < 8; nt++) {
            int cc = bn + wn + nt * 8 + 2 * tg;
            float2 bv = *(const float2*)(bias + cc);
            float* p0 = C + (size_t)r0 * Gn + cc;
            float2 o0 = make_float2(acc[mt][nt][0] + bv.x, acc[mt][nt][1] + bv.y);
            float2 o1 = make_float2(acc[mt][nt][2] + bv.x, acc[mt][nt][3] + bv.y);
            *(float2*)p0            = o0;
            *(float2*)(p0 + 8 * Gn) = o1;
        }
    }
}

// ---------------- 3) persistent bidirectional LSTM (128 blocks, 512 thr) --------
#define RS 264
#define KHO 132
#define SMEM_LSTM ((16*RS + Bn*RS) * sizeof(float))

__global__ __launch_bounds__(512)
void k_lstm(const float* __restrict__ Whh_f, const float* __restrict__ Whh_b)
{
    extern __shared__ float smx[];
    float* Ws = smx;               // [4 gates][4 jj][RS]  (each row: 2 k-halves)
    float* hs = smx + 16 * RS;     // [64 b][RS]

    const int tid = threadIdx.x;
    const int dir = blockIdx.x >> 6;
    const int j0  = (blockIdx.x & 63) << 2;
    const int b   = tid >> 3;
    const int jj  = (tid >> 1) & 3;
    const int kh  = tid & 1;

    const float* Whh = dir ? Whh_b : Whh_f;
    for (int idx = tid; idx < 4096; idx += 512) {
        int g = idx >> 10, j2 = (idx >> 8) & 3, k = idx & 255;
        Ws[(g * 4 + j2) * RS + (k >> 7) * KHO + (k & 127)] =
            Whh[(g * Hn + j0 + j2) * Hn + k];
    }

    if (kh == 0)
        g_h[(0 * 2 + dir) * (Bn * Hn) + b * Hn + j0 + jj] = 0.f;

    float c = 0.f;
    volatile unsigned* vgen = &g_bg[dir];
    unsigned gen = *vgen;

#define GRID_BAR() do {                                                   \
        __syncthreads();                                                  \
        if (tid == 0) {                                                   \
            __threadfence();                                              \
            unsigned tgt = ++gen;                                         \
            if (atomicAdd(&g_bc[dir], 1u) == 63u) {                       \
                g_bc[dir] = 0u;                                           \
                __threadfence();                                          \
                atomicAdd(&g_bg[dir], 1u);                                \
            } else {                                                      \
                while (*vgen != tgt) { }                                  \
                __threadfence();                                          \
            }                                                             \
        }                                                                 \
        __syncthreads();                                                  \
    } while (0)

    GRID_BAR();   // h0 visible everywhere

    const size_t zdir = (size_t)dir * NTOK * Gn;
    const float* hrow = hs + b * RS + kh * KHO;
    const float* w0 = Ws + (0 * 4 + jj) * RS + kh * KHO;
    const float* w1 = Ws + (1 * 4 + jj) * RS + kh * KHO;
    const float* w2 = Ws + (2 * 4 + jj) * RS + kh * KHO;
    const float* w3 = Ws + (3 * 4 + jj) * RS + kh * KHO;

    float z0 = 0.f, z1 = 0.f, z2 = 0.f, z3 = 0.f;
    {
        int t0 = dir ? (Sn - 1) : 0;
        const float* zr = g_zx + zdir + ((size_t)(t0 * Bn + b) << 10) + j0 + jj;
        if (kh == 0) { z0 = zr[0]; z1 = zr[256]; z2 = zr[512]; z3 = zr[768]; }
    }

    for (int st = 0; st < Sn; ++st) {
        const int t   = dir ? (Sn - 1 - st) : st;
        const int par = st & 1;

        const float4* hp = (const float4*)(g_h + (par * 2 + dir) * (Bn * Hn));
#pragma unroll
        for (int i = 0; i < 8; i++) {
            int li = tid + (i << 9);
            float4 v = hp[li];
            int bb = li >> 6, kk = li & 63;
            int khh = kk >> 5, kr = (kk & 31) << 2;
            *(float4*)(hs + bb * RS + khh * KHO + kr) = v;
        }
        __syncthreads();

        float a0 = z0, a1 = z1, a2 = z2, a3 = z3;
#pragma unroll 8
        for (int k = 0; k < 128; k += 4) {
            float4 hv = *(const float4*)(hrow + k);
            float4 wv;
            wv = *(const float4*)(w0 + k);
            a0 += hv.x * wv.x + hv.y * wv.y + hv.z * wv.z + hv.w * wv.w;
            wv = *(const float4*)(w1 + k);
            a1 += hv.x * wv.x + hv.y * wv.y + hv.z * wv.z + hv.w * wv.w;
            wv = *(const float4*)(w2 + k);
            a2 += hv.x * wv.x + hv.y * wv.y + hv.z * wv.z + hv.w * wv.w;
            wv = *(const float4*)(w3 + k);
            a3 += hv.x * wv.x + hv.y * wv.y + hv.z * wv.z + hv.w * wv.w;
        }

        if (st + 1 < Sn) {
            int tn2 = dir ? (Sn - 2 - st) : (st + 1);
            const float* zr = g_zx + zdir + ((size_t)(tn2 * Bn + b) << 10) + j0 + jj;
            if (kh == 0) { z0 = zr[0]; z1 = zr[256]; z2 = zr[512]; z3 = zr[768]; }
        }

        a0 += __shfl_xor_sync(0xffffffffu, a0, 1);
        a1 += __shfl_xor_sync(0xffffffffu, a1, 1);
        a2 += __shfl_xor_sync(0xffffffffu, a2, 1);
        a3 += __shfl_xor_sync(0xffffffffu, a3, 1);

        float ig = 1.f / (1.f + expf(-a0));
        float fg = 1.f / (1.f + expf(-a1));
        float gg = tanhf(a2);
        float og = 1.f / (1.f + expf(-a3));
        c = fg * c + ig * gg;
        float hn = og * tanhf(c);

        int j = j0 + jj;
        if (kh == 0)
            g_h[((par ^ 1) * 2 + dir) * (Bn * Hn) + b * Hn + j] = hn;
        else
            g_hseq[(((size_t)dir * Bn + b) * Sn + t) * Hn + j] = hn;

        GRID_BAR();
    }
#undef GRID_BAR
}

// ---------------- 4) feats = concat(h_f,h_b) @ Wout^T + bout -------------------
__global__ __launch_bounds__(256)
void k_feats(const float* __restrict__ Wout, const float* __restrict__ bout)
{
    __shared__ float Wt[128][33];

    const int tid = threadIdx.x;
    const int tag = tid & 31;
    const int ti  = tid >> 5;
    const int m   = blockIdx.x * 8 + ti;
    const int bb  = m & 63, ss = m >> 6;

    float acc = bout[tag];

    for (int cch = 0; cch < 4; cch++) {
        __syncthreads();
        for (int i = tid; i < 1024; i += 256) {
            int r = i >> 5;
            int k4 = i & 31;
            float4 w = *(const float4*)(Wout + (size_t)r * 512 + cch * 128 + (k4 << 2));
            Wt[(k4 << 2) + 0][r] = w.x;
            Wt[(k4 << 2) + 1][r] = w.y;
            Wt[(k4 << 2) + 2][r] = w.z;
            Wt[(k4 << 2) + 3][r] = w.w;
        }
        __syncthreads();

        const float* hrow;
        if (cch < 2)
            hrow = g_hseq + (((size_t)0 * Bn + bb) * Sn + ss) * Hn + cch * 128;
        else
            hrow = g_hseq + (((size_t)1 * Bn + bb) * Sn + ss) * Hn + (cch - 2) * 128;

#pragma unroll 8
        for (int k = 0; k < 128; k += 4) {
            float4 hv = *(const float4*)(hrow + k);
            acc += hv.x * Wt[k + 0][tag];
            acc += hv.y * Wt[k + 1][tag];
            acc += hv.z * Wt[k + 2][tag];
            acc += hv.w * Wt[k + 3][tag];
        }
    }
    g_feats[((size_t)(bb * Sn) + ss) * Tn + tag] = acc;
}

// ---------------- 5) Viterbi: one warp per batch ------------------------------
__global__ void k_viterbi(const float* __restrict__ trans, float* __restrict__ out)
{
    __shared__ float tr[32][32];
    __shared__ unsigned char bp[Sn][32];

    const int b   = blockIdx.x;
    const int tag = threadIdx.x;

    for (int p = 0; p < 32; p++) tr[p][tag] = trans[p * 32 + tag];
    __syncwarp();

    float v = (tag == 0) ? 0.f : -10000.f;
    const float* fb = g_feats + (size_t)b * Sn * Tn;

    for (int t = 0; t < Sn; t++) {
        float best = -3.4e38f; int arg = 0;
#pragma unroll
        for (int p = 0; p < 32; p++) {
            float vp = __shfl_sync(0xffffffffu, v, p);
            float sc = vp + tr[p][tag];
            if (sc > best) { best = sc; arg = p; }
        }
        bp[t][tag] = (unsigned char)arg;
        v = best + fb[t * 32 + tag];
    }

    float term = v + tr[0][tag];
    float best = -3.4e38f; int lt = 0;
#pragma unroll
    for (int p = 0; p < 32; p++) {
        float tp = __shfl_sync(0xffffffffu, term, p);
        if (tp > best) { best = tp; lt = p; }
    }
    __syncwarp();

    if (tag == 0) {
        int cur = lt;
        for (int t = Sn - 1; t >= 1; --t) {
            out[b * Sn + t] = (float)cur;
            cur = bp[t][cur];
        }
        out[b * Sn + 0] = (float)cur;
        out[NTOK + b]   = best;
    }
}

// ---------------- launcher -----------------------------------------------------
extern "C" void kernel_launch(void* const* d_in, const int* in_sizes, int n_in,
                              void* d_out, int out_size)
{
    const int*   sent  = (const int*)  d_in[0];
    const float* embed = (const float*)d_in[1];
    const float* Wih_f = (const float*)d_in[2];
    const float* Whh_f = (const float*)d_in[3];
    const float* b_f   = (const float*)d_in[4];
    const float* Wih_b = (const float*)d_in[5];
    const float* Whh_b = (const float*)d_in[6];
    const float* b_b   = (const float*)d_in[7];
    const float* Wout  = (const float*)d_in[8];
    const float* bout  = (const float*)d_in[9];
    const float* trans = (const float*)d_in[10];
    float* out = (float*)d_out;
    (void)in_sizes; (void)n_in; (void)out_size;

    // 1) embedding + bf16 hi/lo split of A; W split (tiny)
    k_embed<<<NTOK, 256>>>(sent, embed);
    k_wconv<<<2 * Gn, 256>>>(Wih_f, Wih_b);

    // 2) tensor-core (HMMA) input GEMM, both directions
    dim3 gg(NTOK / 128, Gn / 128, 2);
    k_gemm_mma<<<gg, 256>>>(b_f, b_b);

    // 3) persistent recurrent kernel (128 co-resident blocks, per-dir barriers)
    cudaFuncSetAttribute(k_lstm, cudaFuncAttributeMaxDynamicSharedMemorySize,
                         (int)SMEM_LSTM);
    k_lstm<<<128, 512, SMEM_LSTM>>>(Whh_f, Whh_b);

    // 4) emissions
    k_feats<<<NTOK / 8, 256>>>(Wout, bout);

    // 5) viterbi decode + writeback (paths as float, then scores)
    k_viterbi<<<Bn, 32>>>(trans, out);
}